// round 9
// baseline (speedup 1.0000x reference)
#include <cuda_runtime.h>

// Problem constants
#define TT     2048
#define CELLS  2048
#define NPAIR  (CELLS / 2)    // 1024 cell-pairs
#define NSEG   128
#define SEGLEN (TT / NSEG)    // 16
#define CHUNK  8
#define NCHUNK (TT / CHUNK)   // 256

// Scratch: boundary states entering each segment (seg 1..NSEG-1).
// Layout float2[NSEG*CELLS]; pass1 writes it as float4 per cell-pair
// ((S1,S2) of cell 2p, then cell 2p+1) which matches exactly.
__device__ float2 g_bound[NSEG * CELLS];

// ---------------------------------------------------------------------------
// Pass 1: serial boundary scan, 2 adjacent cells per thread (ILP=2 to fill
// the single warp's dependency-stall slots). 32 blocks x 32 threads -> one
// warp per SM, exclusive SMSP. 4-stage rotating register prefetch (CHUNK=8,
// 3 chunks = 24 steps ahead), one LDG.128 interleaved per step.
// Shortened S1 chain (3 dependent ops):
//   S1' = max( fma(S1, c1 - E/smax, P), max(fma(S1, c1, P - E), 0) )
// S2 clamp dropped in-scan: fma(S2, c2, k2*S1) >= 0 always.
// ---------------------------------------------------------------------------
__global__ __launch_bounds__(32, 1)
void pass1_kernel(const float4* __restrict__ F4,   // forcings [T, NPAIR]
                  const float4* __restrict__ S04,  // initial states [NPAIR]
                  const float4* __restrict__ P4)   // params [CELLS]
{
    const int pair = blockIdx.x * 32 + threadIdx.x;

    const float4 ua = P4[2 * pair + 0];
    const float4 ub = P4[2 * pair + 1];

    const float smaxa = 10.0f  + 490.0f  * ua.x;
    const float k1a   = 0.01f  + 0.89f   * ua.y;
    const float k2a   = 0.001f + 0.199f  * ua.z;
    const float kba   = 0.001f + 0.099f  * ua.w;
    const float smaxb = 10.0f  + 490.0f  * ub.x;
    const float k1b   = 0.01f  + 0.89f   * ub.y;
    const float k2b   = 0.001f + 0.199f  * ub.z;
    const float kbb   = 0.001f + 0.099f  * ub.w;

    const float inva = 1.0f / smaxa,      invb = 1.0f / smaxb;
    const float c1a  = 1.0f - k1a - k2a,  c1b  = 1.0f - k1b - k2b;
    const float c2a  = 1.0f - kba,        c2b  = 1.0f - kbb;

    const float4 s0 = S04[pair];
    float S1a = s0.x, S2a = s0.y, S1b = s0.z, S2b = s0.w;

    const float4* __restrict__ F = F4 + pair;

#define SCAN_STEP2(fv)                                           \
    do {                                                         \
        const float Pa = (fv).x, Ea = (fv).y;                    \
        const float Pb = (fv).z, Eb = (fv).w;                    \
        const float caa  = c1a - Ea * inva;                      \
        const float cab  = c1b - Eb * invb;                      \
        const float pmea = Pa - Ea;                              \
        const float pmeb = Pb - Eb;                              \
        const float prca = k2a * S1a;                            \
        const float prcb = k2b * S1b;                            \
        const float t1a  = fmaf(S1a, caa, Pa);                   \
        const float t1b  = fmaf(S1b, cab, Pb);                   \
        const float t2a  = fmaf(S1a, c1a, pmea);                 \
        const float t2b  = fmaf(S1b, c1b, pmeb);                 \
        S1a = fmaxf(t1a, fmaxf(t2a, 0.0f));                      \
        S1b = fmaxf(t1b, fmaxf(t2b, 0.0f));                      \
        S2a = fmaf(S2a, c2a, prca);                              \
        S2b = fmaf(S2b, c2b, prcb);                              \
    } while (0)

#define LOADC(buf, ci)                                           \
    do {                                                         \
        const float4* Fp = F + (size_t)(ci) * CHUNK * NPAIR;     \
        _Pragma("unroll")                                        \
        for (int i = 0; i < CHUNK; i++)                          \
            (buf)[i] = Fp[i * NPAIR];                            \
    } while (0)

    // Process chunk pci while loading chunk lci (one LDG.128 per step).
    // lci clamped at tail (redundant reload, never consumed).
    // Boundary after every odd chunk: 16 steps -> seg (pci+1)/2.
#define PROC_LOAD(pbuf, pci, lbuf, lci_raw)                      \
    do {                                                         \
        const int lci = ((lci_raw) < NCHUNK) ? (lci_raw)         \
                                             : (NCHUNK - 1);     \
        const float4* Fp = F + (size_t)lci * CHUNK * NPAIR;      \
        _Pragma("unroll")                                        \
        for (int i = 0; i < CHUNK; i++) {                        \
            (lbuf)[i] = Fp[i * NPAIR];                           \
            SCAN_STEP2((pbuf)[i]);                               \
        }                                                        \
        if (((pci) & 1) && (pci) != NCHUNK - 1) {                \
            const int segi = ((pci) + 1) >> 1;                   \
            reinterpret_cast<float4*>(g_bound)[segi * NPAIR      \
                + pair] = make_float4(S1a, S2a, S1b, S2b);       \
        }                                                        \
    } while (0)

    float4 bufA[CHUNK], bufB[CHUNK], bufC[CHUNK], bufD[CHUNK];

    LOADC(bufA, 0);
    LOADC(bufB, 1);
    LOADC(bufC, 2);

#pragma unroll 1
    for (int c = 0; c < NCHUNK; c += 4) {
        PROC_LOAD(bufA, c,     bufD, c + 3);
        PROC_LOAD(bufB, c + 1, bufA, c + 4);
        PROC_LOAD(bufC, c + 2, bufB, c + 5);
        PROC_LOAD(bufD, c + 3, bufC, c + 6);
    }
#undef SCAN_STEP2
#undef LOADC
#undef PROC_LOAD
}

// ---------------------------------------------------------------------------
// Pass 2: parallel segment replay. One thread = (cell, segment).
// Replays SEGLEN steps from the boundary state, writing fluxes AND states
// with reference-faithful arithmetic. At its memory roofline (~21us).
// ---------------------------------------------------------------------------
__global__ __launch_bounds__(256)
void pass2_kernel(const float2* __restrict__ F2,   // forcings [T, CELLS]
                  const float2* __restrict__ S02,  // initial states [CELLS]
                  const float4* __restrict__ P4,   // params [CELLS]
                  float4* __restrict__ FX4,        // fluxes [T, CELLS]
                  float2* __restrict__ ST2)        // states [T, CELLS]
{
    const int cell = blockIdx.x * 256 + threadIdx.x;
    const int seg  = blockIdx.y;
    const int t0   = seg * SEGLEN;

    const float4 u = P4[cell];
    const float smax = 10.0f  + 490.0f  * u.x;
    const float k1   = 0.01f  + 0.89f   * u.y;
    const float k2   = 0.001f + 0.199f  * u.z;
    const float kb   = 0.001f + 0.099f  * u.w;
    const float inv  = 1.0f / smax;

    float2 s = (seg == 0) ? S02[cell] : g_bound[seg * CELLS + cell];
    float S1 = s.x, S2 = s.y;

    const float2* __restrict__ F  = F2  + (size_t)t0 * CELLS + cell;
    float4*       __restrict__ FX = FX4 + (size_t)t0 * CELLS + cell;
    float2*       __restrict__ ST = ST2 + (size_t)t0 * CELLS + cell;

#pragma unroll 4
    for (int i = 0; i < SEGLEN; i++) {
        const float2 f  = F[i * CELLS];
        const float P   = f.x;
        const float PET = f.y;

        const float frac = fminf(S1 * inv, 1.0f);   // S1 >= 0 always
        const float et   = PET * frac;
        const float q1   = k1 * S1;
        const float perc = k2 * S1;
        const float qb   = kb * S2;

        FX[i * CELLS] = make_float4(et, q1, perc, qb);

        S1 = fmaxf(S1 + P - et - q1 - perc, 0.0f);
        S2 = fmaxf(S2 + perc - qb, 0.0f);

        ST[i * CELLS] = make_float2(S1, S2);
    }
}

extern "C" void kernel_launch(void* const* d_in, const int* in_sizes, int n_in,
                              void* d_out, int out_size)
{
    const float* forcings = (const float*)d_in[0];   // [T,B,H,2]
    const float* states0  = (const float*)d_in[1];   // [B,H,2]
    const float* params   = (const float*)d_in[2];   // [B,H,4]

    float* out = (float*)d_out;
    float* fluxes_out = out;                                   // [T,B,H,4]
    float* states_out = out + (size_t)TT * CELLS * 4;          // [T,B,H,2]

    pass1_kernel<<<NPAIR / 32, 32>>>(
        reinterpret_cast<const float4*>(forcings),
        reinterpret_cast<const float4*>(states0),
        reinterpret_cast<const float4*>(params));

    pass2_kernel<<<dim3(CELLS / 256, NSEG), 256>>>(
        reinterpret_cast<const float2*>(forcings),
        reinterpret_cast<const float2*>(states0),
        reinterpret_cast<const float4*>(params),
        reinterpret_cast<float4*>(fluxes_out),
        reinterpret_cast<float2*>(states_out));
}